// round 3
// baseline (speedup 1.0000x reference)
#include <cuda_runtime.h>

typedef unsigned long long ull;

// ---- packed f32x2 helpers (FFMA2 only reachable via PTX, per SASS_QUICKREF) ----
__device__ __forceinline__ ull pk2(float lo, float hi) {
    ull r; asm("mov.b64 %0,{%1,%2};" : "=l"(r) : "f"(lo), "f"(hi)); return r;
}
__device__ __forceinline__ void up2(ull a, float& x, float& y) {
    asm("mov.b64 {%0,%1},%2;" : "=f"(x), "=f"(y) : "l"(a));
}
__device__ __forceinline__ ull fma2(ull a, ull b, ull c) {
    ull d; asm("fma.rn.f32x2 %0,%1,%2,%3;" : "=l"(d) : "l"(a), "l"(b), "l"(c)); return d;
}

// Each thread processes 2 rows (20 input floats, 10 output floats).
// Element-pairs across the two rows share one f32x2 lane.
__global__ void __launch_bounds__(256) simplenn_kernel(
    const float* __restrict__ x,
    const float* __restrict__ gate,
    const float* __restrict__ w1,   // (2,64) row-major
    const float* __restrict__ b1,   // (64,)
    const float* __restrict__ w2,   // (64,1)
    const float* __restrict__ b2,   // (1,)
    float* __restrict__ out,        // (B,5)
    int npairs)
{
    // Duplicated-pair weight table: per hidden unit j, [ (u,u), (v,v), (c,c), (w,w) ] = 32B
    __shared__ __align__(16) ull wpk[64][4];

    int tid = threadIdx.x;
    if (tid < 64) {
        float u = w1[tid];        // w1[0][j]
        float v = w1[64 + tid];   // w1[1][j]
        float c = b1[tid];
        float w = w2[tid];
        wpk[tid][0] = pk2(u, u);
        wpk[tid][1] = pk2(v, v);
        wpk[tid][2] = pk2(c, c);
        wpk[tid][3] = pk2(w, w);
    }

    // argmax(gate_logits) — runtime-constant, uniform across all threads (L1/L2-cached)
    float g0 = gate[0], g1 = gate[1], g2 = gate[2], g3 = gate[3];
    int idx = 0; float best = g0;
    if (g1 > best) { best = g1; idx = 1; }
    if (g2 > best) { best = g2; idx = 2; }
    if (g3 > best) { best = g3; idx = 3; }

    __syncthreads();

    int t = blockIdx.x * 256 + tid;
    if (t >= npairs) return;

    // Load 2 rows = 20 floats, 80B per thread, 16B-aligned, fully coalesced
    float v20[20];
    const float4* xp = (const float4*)(x + (size_t)t * 20);
    #pragma unroll
    for (int q = 0; q < 5; q++) {
        float4 f = xp[q];
        v20[4*q+0] = f.x; v20[4*q+1] = f.y; v20[4*q+2] = f.z; v20[4*q+3] = f.w;
    }

    // Apply selected transform (uniform branch; MUFU-based intrinsics)
    if (idx == 1) {
        #pragma unroll
        for (int i = 0; i < 20; i++) v20[i] = __logf(v20[i]);
    } else if (idx == 2) {
        #pragma unroll
        for (int i = 0; i < 20; i++) v20[i] = __expf(v20[i]);
    } else if (idx == 3) {
        #pragma unroll
        for (int i = 0; i < 20; i++) v20[i] = __sinf(v20[i]);
    }

    // Pack: lane pair i holds element i of row0 (lo) and row1 (hi).
    // A = wi (sel[:, i]), B = pi (sel[:, 5+i])
    ull A[5], Bp[5], acc[5];
    float bias = b2[0];
    ull bias2 = pk2(bias, bias);
    #pragma unroll
    for (int i = 0; i < 5; i++) {
        A[i]   = pk2(v20[i],      v20[10 + i]);
        Bp[i]  = pk2(v20[5 + i],  v20[15 + i]);
        acc[i] = bias2;  // fold b2 into the accumulator
    }

    // 64 hidden units; 2x LDS.128 broadcast + 15 FFMA2 + 10 FMNMX per unit
    #pragma unroll 8
    for (int j = 0; j < 64; j++) {
        const ulonglong2* wp = (const ulonglong2*)wpk[j];
        ulonglong2 p0 = wp[0];   // (uu, vv)
        ulonglong2 p1 = wp[1];   // (cc, ww)
        ull uu = p0.x, vv = p0.y, cc = p1.x, ww = p1.y;
        #pragma unroll
        for (int i = 0; i < 5; i++) {
            ull t2 = fma2(A[i], uu, fma2(Bp[i], vv, cc));
            float h0, h1;
            up2(t2, h0, h1);
            h0 = fmaxf(h0, 0.0f);   // FMNMX on alu pipe, overlaps fma pipe
            h1 = fmaxf(h1, 0.0f);
            acc[i] = fma2(pk2(h0, h1), ww, acc[i]);
        }
    }

    // Unpack and store 10 contiguous floats (8B-aligned -> 5x st.v2)
    float r0[5], r1[5];
    #pragma unroll
    for (int i = 0; i < 5; i++) up2(acc[i], r0[i], r1[i]);

    float2* op = (float2*)(out + (size_t)t * 10);
    op[0] = make_float2(r0[0], r0[1]);
    op[1] = make_float2(r0[2], r0[3]);
    op[2] = make_float2(r0[4], r1[0]);
    op[3] = make_float2(r1[1], r1[2]);
    op[4] = make_float2(r1[3], r1[4]);
}

extern "C" void kernel_launch(void* const* d_in, const int* in_sizes, int n_in,
                              void* d_out, int out_size) {
    const float* x    = (const float*)d_in[0];
    const float* gate = (const float*)d_in[1];
    const float* w1   = (const float*)d_in[2];
    const float* b1   = (const float*)d_in[3];
    const float* w2   = (const float*)d_in[4];
    const float* b2   = (const float*)d_in[5];
    float* out = (float*)d_out;

    int nrows  = in_sizes[0] / 10;   // BATCH
    int npairs = nrows / 2;          // 2 rows per thread (BATCH is even)
    int blocks = (npairs + 255) / 256;

    simplenn_kernel<<<blocks, 256>>>(x, gate, w1, b1, w2, b2, out, npairs);
}

// round 4
// speedup vs baseline: 1.0371x; 1.0371x over previous
#include <cuda_runtime.h>

typedef unsigned long long ull;

// ---- packed f32x2 helpers (FFMA2 only reachable via PTX, per SASS_QUICKREF) ----
__device__ __forceinline__ ull pk2(float lo, float hi) {
    ull r; asm("mov.b64 %0,{%1,%2};" : "=l"(r) : "f"(lo), "f"(hi)); return r;
}
__device__ __forceinline__ void up2(ull a, float& x, float& y) {
    asm("mov.b64 {%0,%1},%2;" : "=f"(x), "=f"(y) : "l"(a));
}
__device__ __forceinline__ ull fma2(ull a, ull b, ull c) {
    ull d; asm("fma.rn.f32x2 %0,%1,%2,%3;" : "=l"(d) : "l"(a), "l"(b), "l"(c)); return d;
}

// Each thread processes 4 rows (40 input floats, 20 output floats).
// Rows (0,1) and (2,3) form f32x2 lane pairs -> 10 independent (A,B,acc) chains.
__global__ void __launch_bounds__(128) simplenn_kernel(
    const float* __restrict__ x,
    const float* __restrict__ gate,
    const float* __restrict__ w1,   // (2,64) row-major
    const float* __restrict__ b1,   // (64,)
    const float* __restrict__ w2,   // (64,1)
    const float* __restrict__ b2,   // (1,)
    float* __restrict__ out,        // (B,5)
    int nquads)
{
    // Duplicated-pair weight table: per hidden unit j, [ (u,u), (v,v), (c,c), (w,w) ] = 32B
    __shared__ __align__(16) ull wpk[64][4];

    int tid = threadIdx.x;
    if (tid < 64) {
        float u = w1[tid];        // w1[0][j]
        float v = w1[64 + tid];   // w1[1][j]
        float c = b1[tid];
        float w = w2[tid];
        wpk[tid][0] = pk2(u, u);
        wpk[tid][1] = pk2(v, v);
        wpk[tid][2] = pk2(c, c);
        wpk[tid][3] = pk2(w, w);
    }

    // argmax(gate_logits) — runtime-constant, uniform across all threads
    float g0 = gate[0], g1 = gate[1], g2 = gate[2], g3 = gate[3];
    int idx = 0; float best = g0;
    if (g1 > best) { best = g1; idx = 1; }
    if (g2 > best) { best = g2; idx = 2; }
    if (g3 > best) { best = g3; idx = 3; }

    __syncthreads();

    int t = blockIdx.x * 128 + tid;
    if (t >= nquads) return;

    // Load 4 rows = 40 floats, 160B per thread, 16B-aligned, coalesced
    float v40[40];
    const float4* xp = (const float4*)(x + (size_t)t * 40);
    #pragma unroll
    for (int q = 0; q < 10; q++) {
        float4 f = xp[q];
        v40[4*q+0] = f.x; v40[4*q+1] = f.y; v40[4*q+2] = f.z; v40[4*q+3] = f.w;
    }

    // Apply selected transform (uniform branch; MUFU-based intrinsics)
    if (idx == 1) {
        #pragma unroll
        for (int i = 0; i < 40; i++) v40[i] = __logf(v40[i]);
    } else if (idx == 2) {
        #pragma unroll
        for (int i = 0; i < 40; i++) v40[i] = __expf(v40[i]);
    } else if (idx == 3) {
        #pragma unroll
        for (int i = 0; i < 40; i++) v40[i] = __sinf(v40[i]);
    }

    // Pack 10 chains: p in [0,5) -> rows(0,1), p in [5,10) -> rows(2,3).
    // Row r occupies v40[10r .. 10r+9]; A = wi (cols 0..4), B = pi (cols 5..9).
    ull A[10], Bp[10], acc[10];
    float bias = b2[0];
    ull bias2 = pk2(bias, bias);
    #pragma unroll
    for (int i = 0; i < 5; i++) {
        A[i]      = pk2(v40[i],          v40[10 + i]);
        Bp[i]     = pk2(v40[5 + i],      v40[15 + i]);
        A[5 + i]  = pk2(v40[20 + i],     v40[30 + i]);
        Bp[5 + i] = pk2(v40[25 + i],     v40[35 + i]);
        acc[i]     = bias2;   // fold b2 into the accumulator
        acc[5 + i] = bias2;
    }

    // 64 hidden units; 2x LDS.128 broadcast + 30 FFMA2 + 20 FMNMX per unit
    #pragma unroll 8
    for (int j = 0; j < 64; j++) {
        const ulonglong2* wp = (const ulonglong2*)wpk[j];
        ulonglong2 p0 = wp[0];   // (uu, vv)
        ulonglong2 p1 = wp[1];   // (cc, ww)
        ull uu = p0.x, vv = p0.y, cc = p1.x, ww = p1.y;
        #pragma unroll
        for (int p = 0; p < 10; p++) {
            ull t2 = fma2(A[p], uu, fma2(Bp[p], vv, cc));
            float h0, h1;
            up2(t2, h0, h1);
            h0 = fmaxf(h0, 0.0f);   // FMNMX on alu pipe, overlaps fma pipe
            h1 = fmaxf(h1, 0.0f);
            acc[p] = fma2(pk2(h0, h1), ww, acc[p]);
        }
    }

    // Unpack: acc[p] (p<5) -> (row0 out[p], row1 out[p]); p>=5 -> rows 2,3.
    // Output layout per thread: 20 contiguous floats = 5 float4 stores.
    float o[20];
    #pragma unroll
    for (int i = 0; i < 5; i++) {
        up2(acc[i],     o[i],      o[5 + i]);
        up2(acc[5 + i], o[10 + i], o[15 + i]);
    }

    float4* op = (float4*)(out + (size_t)t * 20);
    #pragma unroll
    for (int q = 0; q < 5; q++)
        op[q] = make_float4(o[4*q+0], o[4*q+1], o[4*q+2], o[4*q+3]);
}

extern "C" void kernel_launch(void* const* d_in, const int* in_sizes, int n_in,
                              void* d_out, int out_size) {
    const float* x    = (const float*)d_in[0];
    const float* gate = (const float*)d_in[1];
    const float* w1   = (const float*)d_in[2];
    const float* b1   = (const float*)d_in[3];
    const float* w2   = (const float*)d_in[4];
    const float* b2   = (const float*)d_in[5];
    float* out = (float*)d_out;

    int nrows  = in_sizes[0] / 10;   // BATCH
    int nquads = nrows / 4;          // 4 rows per thread (BATCH % 4 == 0)
    int blocks = (nquads + 127) / 128;

    simplenn_kernel<<<blocks, 128>>>(x, gate, w1, b1, w2, b2, out, nquads);
}

// round 5
// speedup vs baseline: 1.1273x; 1.0870x over previous
#include <cuda_runtime.h>

typedef unsigned long long ull;

// ---- packed f32x2 helpers (only reachable via PTX, per SASS_QUICKREF) ----
__device__ __forceinline__ ull pk2(float lo, float hi) {
    ull r; asm("mov.b64 %0,{%1,%2};" : "=l"(r) : "f"(lo), "f"(hi)); return r;
}
__device__ __forceinline__ void up2(ull a, float& x, float& y) {
    asm("mov.b64 {%0,%1},%2;" : "=f"(x), "=f"(y) : "l"(a));
}
__device__ __forceinline__ ull fma2(ull a, ull b, ull c) {
    ull d; asm("fma.rn.f32x2 %0,%1,%2,%3;" : "=l"(d) : "l"(a), "l"(b), "l"(c)); return d;
}
__device__ __forceinline__ ull add2(ull a, ull b) {
    ull d; asm("add.rn.f32x2 %0,%1,%2;" : "=l"(d) : "l"(a), "l"(b)); return d;
}

// Each thread processes 2 rows (20 input floats, 10 output floats).
// Hidden units sign-partitioned: w2>=0 units in slots [0,NPOS), w2<0 in [NPOS,64).
// Weights pre-scaled by |w2| so the accumulate is a pure packed ADD (2 RF banks, rt2)
// instead of an FMA (6 banks, rt3): out = b2 + sum_pos relu(t') - sum_neg relu(t').
__global__ void __launch_bounds__(128) simplenn_kernel(
    const float* __restrict__ x,
    const float* __restrict__ gate,
    const float* __restrict__ w1,   // (2,64) row-major
    const float* __restrict__ b1,   // (64,)
    const float* __restrict__ w2,   // (64,1)
    const float* __restrict__ b2,   // (1,)
    float* __restrict__ out,        // (B,5)
    int npairs)
{
    // Scaled, duplicated-pair weights in partitioned order
    __shared__ ull wu[64], wv[64], wc[64];
    __shared__ int s_npos0, s_npos1, s_NPOS;

    int tid  = threadIdx.x;
    int lane = tid & 31;

    // ---- build phase: scale by |w2|, sign-partition via ballot compaction ----
    unsigned m = 0;
    float su = 0.f, sv = 0.f, sc = 0.f;
    bool pos = true;
    if (tid < 64) {
        float u = w1[tid];
        float v = w1[64 + tid];
        float c = b1[tid];
        float w = w2[tid];
        float aw = fabsf(w);
        pos = (w >= 0.0f);
        su = aw * u; sv = aw * v; sc = aw * c;
        m = __ballot_sync(0xffffffffu, pos);   // warps 0,1 fully inside tid<64
        if (lane == 0) {
            if (tid < 32) s_npos0 = __popc(m);
            else          s_npos1 = __popc(m);
        }
    }
    __syncthreads();

    if (tid < 64) {
        int npos0 = s_npos0;
        int NPOS  = npos0 + s_npos1;
        unsigned below = (1u << lane) - 1u;
        int slot;
        if (pos) {
            slot = __popc(m & below) + (tid >= 32 ? npos0 : 0);
        } else {
            slot = NPOS + __popc(~m & below) + (tid >= 32 ? (32 - npos0) : 0);
        }
        wu[slot] = pk2(su, su);
        wv[slot] = pk2(sv, sv);
        wc[slot] = pk2(sc, sc);
        if (tid == 0) s_NPOS = NPOS;
    }

    // argmax(gate_logits) — runtime-constant, uniform across all threads
    float g0 = gate[0], g1 = gate[1], g2 = gate[2], g3 = gate[3];
    int idx = 0; float best = g0;
    if (g1 > best) { best = g1; idx = 1; }
    if (g2 > best) { best = g2; idx = 2; }
    if (g3 > best) { best = g3; idx = 3; }

    __syncthreads();

    int t = blockIdx.x * 128 + tid;
    if (t >= npairs) return;

    // Load 2 rows = 20 floats, 80B per thread, 16B-aligned, coalesced
    float v20[20];
    const float4* xp = (const float4*)(x + (size_t)t * 20);
    #pragma unroll
    for (int q = 0; q < 5; q++) {
        float4 f = xp[q];
        v20[4*q+0] = f.x; v20[4*q+1] = f.y; v20[4*q+2] = f.z; v20[4*q+3] = f.w;
    }

    // Apply selected transform (uniform branch; MUFU-based intrinsics)
    if (idx == 1) {
        #pragma unroll
        for (int i = 0; i < 20; i++) v20[i] = __logf(v20[i]);
    } else if (idx == 2) {
        #pragma unroll
        for (int i = 0; i < 20; i++) v20[i] = __expf(v20[i]);
    } else if (idx == 3) {
        #pragma unroll
        for (int i = 0; i < 20; i++) v20[i] = __sinf(v20[i]);
    }

    // 5 chains: chain i = element i of (row0, row1) packed in one f32x2 lane
    ull A[5], Bp[5], accP[5], accN[5];
    float bias = b2[0];
    ull bias2 = pk2(bias, bias);
    #pragma unroll
    for (int i = 0; i < 5; i++) {
        A[i]    = pk2(v20[i],     v20[10 + i]);
        Bp[i]   = pk2(v20[5 + i], v20[15 + i]);
        accP[i] = bias2;   // fold b2 into the positive accumulator
        accN[i] = 0;
    }

    int NPOS = s_NPOS;

    // Positive-w2 units: accP += relu(t')   (packed ADD accumulate)
    #pragma unroll 4
    for (int j = 0; j < NPOS; j++) {
        ull uu = wu[j], vv = wv[j], cc = wc[j];
        #pragma unroll
        for (int i = 0; i < 5; i++) {
            ull t2 = fma2(A[i], uu, fma2(Bp[i], vv, cc));
            float h0, h1;
            up2(t2, h0, h1);
            h0 = fmaxf(h0, 0.0f);   // FMNMX w/ imm 0 — 1 RF read, alu pipe
            h1 = fmaxf(h1, 0.0f);
            accP[i] = add2(accP[i], pk2(h0, h1));
        }
    }
    // Negative-w2 units: accN += relu(t')
    #pragma unroll 4
    for (int j = NPOS; j < 64; j++) {
        ull uu = wu[j], vv = wv[j], cc = wc[j];
        #pragma unroll
        for (int i = 0; i < 5; i++) {
            ull t2 = fma2(A[i], uu, fma2(Bp[i], vv, cc));
            float h0, h1;
            up2(t2, h0, h1);
            h0 = fmaxf(h0, 0.0f);
            h1 = fmaxf(h1, 0.0f);
            accN[i] = add2(accN[i], pk2(h0, h1));
        }
    }

    // out = accP - accN, unpack and store 10 contiguous floats
    float r0[5], r1[5];
    #pragma unroll
    for (int i = 0; i < 5; i++) {
        float p0, p1, n0, n1;
        up2(accP[i], p0, p1);
        up2(accN[i], n0, n1);
        r0[i] = p0 - n0;
        r1[i] = p1 - n1;
    }

    float2* op = (float2*)(out + (size_t)t * 10);
    op[0] = make_float2(r0[0], r0[1]);
    op[1] = make_float2(r0[2], r0[3]);
    op[2] = make_float2(r0[4], r1[0]);
    op[3] = make_float2(r1[1], r1[2]);
    op[4] = make_float2(r1[3], r1[4]);
}

extern "C" void kernel_launch(void* const* d_in, const int* in_sizes, int n_in,
                              void* d_out, int out_size) {
    const float* x    = (const float*)d_in[0];
    const float* gate = (const float*)d_in[1];
    const float* w1   = (const float*)d_in[2];
    const float* b1   = (const float*)d_in[3];
    const float* w2   = (const float*)d_in[4];
    const float* b2   = (const float*)d_in[5];
    float* out = (float*)d_out;

    int nrows  = in_sizes[0] / 10;   // BATCH
    int npairs = nrows / 2;          // 2 rows per thread (BATCH is even)
    int blocks = (npairs + 127) / 128;

    simplenn_kernel<<<blocks, 128>>>(x, gate, w1, b1, w2, b2, out, npairs);
}